// round 12
// baseline (speedup 1.0000x reference)
#include <cuda_runtime.h>
#include <math.h>

// Problem constants
#define FEAT 384
#define FFN  768
#define ZDIM 384
#define HID  192
#define BB   4
#define ROWS 512

// GEMM tiling: 32x32x32 tiles, 64 threads, per-thread 4x4, K-vectorized f32x2
#define BM 32
#define BN 32
#define BK 32

typedef unsigned long long ull;

// ---------------- scratch ----------------
__device__ __align__(16) float g_xh[ROWS*ZDIM];
__device__ __align__(16) float g_z [ROWS*ZDIM];
__device__ __align__(16) float g_henc[ROWS*HID];
__device__ __align__(16) float g_w   [ROWS*HID];
__device__ __align__(16) float g_XV  [ROWS*FEAT];
__device__ __align__(16) float g_c0  [ZDIM];
__device__ float g_d0  [ROWS];
__device__ float g_d1b [ROWS];
__device__ float g_alpha[ROWS];
__device__ float g_beta [ROWS];
__device__ __align__(16) float g_T [BB*ZDIM];

// ---------------- helpers ----------------
__device__ __forceinline__ float gelu_f(float x) {
    return 0.5f * x * (1.0f + erff(x * 0.70710678118654752440f));
}
__device__ __forceinline__ void fma2(ull &acc, ull a, ull b) {
    asm("fma.rn.f32x2 %0, %1, %2, %0;" : "+l"(acc) : "l"(a), "l"(b));
}
__device__ __forceinline__ float accsum(ull v) {
    float lo, hi;
    asm("mov.b64 {%0,%1}, %2;" : "=f"(lo), "=f"(hi) : "l"(v));
    return lo + hi;
}

// ============ K1: h = gelu(x @ U_w + U_b) split -> g_xh | g_z ; bid 384 = c0 ============
__global__ __launch_bounds__(64) void k1_gemm(const float* __restrict__ x,
                                              const float* __restrict__ U_w,
                                              const float* __restrict__ U_b,
                                              const float* __restrict__ enc_b,
                                              const float* __restrict__ dec_w,
                                              const float* __restrict__ dec_b) {
    if (blockIdx.x == 384) {
        // c0 = gelu(enc_b) @ dec_w + dec_b
        __shared__ float sg[HID];
        const int t = threadIdx.x;
        for (int h = t; h < HID; h += 64) sg[h] = gelu_f(enc_b[h]);
        __syncthreads();
        for (int f = t; f < ZDIM; f += 64) {
            float acc = dec_b[f];
            #pragma unroll 4
            for (int h = 0; h < HID; h++) acc += sg[h] * dec_w[h*ZDIM + f];
            g_c0[f] = acc;
        }
        return;
    }
    __shared__ __align__(16) float As[2][BM][36];
    __shared__ __align__(16) float Bs[2][BN][36];
    const int bid = blockIdx.x;
    const int n0 = (bid % 24) * BN;       // 768/32 = 24 n-tiles
    const int m0 = (bid / 24) * BM;       // 512/32 = 16 m-tiles
    const int t  = threadIdx.x;
    const int tx = t & 7, ty = t >> 3;
    const int lrow = t >> 1, half = t & 1;
    const int sw = lrow >> 2;             // swizzle key for loader

    ull acc[4][4];
    #pragma unroll
    for (int m = 0; m < 4; m++)
        #pragma unroll
        for (int n = 0; n < 4; n++) acc[m][n] = 0ULL;

    float4 sa[4], sb[4];
    const float* Arow = x + (m0 + lrow)*FEAT + half*16;
    const float* Bkrow = U_w + lrow*FFN + n0 + half*16;   // k-row = lrow

    // prologue: tile 0
    #pragma unroll
    for (int j = 0; j < 4; j++) sa[j] = *(const float4*)(Arow + 4*j);
    #pragma unroll
    for (int j = 0; j < 4; j++) sb[j] = *(const float4*)(Bkrow + 4*j);
    #pragma unroll
    for (int j = 0; j < 4; j++)
        *(float4*)&As[0][lrow][((4*half + j) ^ sw) * 4] = sa[j];
    #pragma unroll
    for (int j = 0; j < 4; j++) {
        const int cb = (sw ^ (4*half + j)) * 4 + (lrow & 3);
        const int nl = half*16 + 4*j;
        Bs[0][nl+0][cb] = sb[j].x;
        Bs[0][nl+1][cb] = sb[j].y;
        Bs[0][nl+2][cb] = sb[j].z;
        Bs[0][nl+3][cb] = sb[j].w;
    }
    __syncthreads();

    int buf = 0;
    #pragma unroll 1
    for (int kt = 0; kt < FEAT/BK; kt++) {
        if (kt < FEAT/BK - 1) {
            const int kb = (kt+1)*BK;
            #pragma unroll
            for (int j = 0; j < 4; j++) sa[j] = *(const float4*)(Arow + kb + 4*j);
            #pragma unroll
            for (int j = 0; j < 4; j++) sb[j] = *(const float4*)(Bkrow + kb*FFN + 4*j);
        }
        #pragma unroll
        for (int q = 0; q < 8; q++) {
            ulonglong2 av[4], bv[4];
            #pragma unroll
            for (int m = 0; m < 4; m++)
                av[m] = *(const ulonglong2*)&As[buf][4*ty + m][(q ^ ty) * 4];
            #pragma unroll
            for (int n = 0; n < 4; n++)
                bv[n] = *(const ulonglong2*)&Bs[buf][4*tx + n][(q ^ tx) * 4];
            #pragma unroll
            for (int m = 0; m < 4; m++)
                #pragma unroll
                for (int n = 0; n < 4; n++) {
                    fma2(acc[m][n], av[m].x, bv[n].x);
                    fma2(acc[m][n], av[m].y, bv[n].y);
                }
        }
        if (kt < FEAT/BK - 1) {
            const int nb = buf ^ 1;
            #pragma unroll
            for (int j = 0; j < 4; j++)
                *(float4*)&As[nb][lrow][((4*half + j) ^ sw) * 4] = sa[j];
            #pragma unroll
            for (int j = 0; j < 4; j++) {
                const int cb = (sw ^ (4*half + j)) * 4 + (lrow & 3);
                const int nl = half*16 + 4*j;
                Bs[nb][nl+0][cb] = sb[j].x;
                Bs[nb][nl+1][cb] = sb[j].y;
                Bs[nb][nl+2][cb] = sb[j].z;
                Bs[nb][nl+3][cb] = sb[j].w;
            }
            __syncthreads();
            buf ^= 1;
        }
    }

    // epilogue: bias + gelu, split store
    const int gcol = n0 + 4*tx;
    const int grow = m0 + 4*ty;
    const float4 b4 = *(const float4*)(U_b + gcol);
    float* dst; int cc;
    if (gcol < ZDIM) { dst = g_xh; cc = gcol; } else { dst = g_z; cc = gcol - ZDIM; }
    #pragma unroll
    for (int m = 0; m < 4; m++) {
        float4 r;
        r.x = gelu_f(accsum(acc[m][0]) + b4.x);
        r.y = gelu_f(accsum(acc[m][1]) + b4.y);
        r.z = gelu_f(accsum(acc[m][2]) + b4.z);
        r.w = gelu_f(accsum(acc[m][3]) + b4.w);
        *(float4*)&dst[(grow + m)*ZDIM + cc] = r;
    }
}

// ============ K2: LayerNorm rows of g_z (in place) + d0, d1b dots ============
__global__ __launch_bounds__(128) void k2_ln(const float* __restrict__ ln_w,
                                             const float* __restrict__ ln_b,
                                             const float* __restrict__ dec_b) {
    const int row = blockIdx.x;
    const int t = threadIdx.x;
    __shared__ float red[128];
    float v[3];
    #pragma unroll
    for (int i = 0; i < 3; i++) v[i] = g_z[row*ZDIM + t + i*128];

    float s = v[0] + v[1] + v[2];
    red[t] = s; __syncthreads();
    for (int st = 64; st > 0; st >>= 1) { if (t < st) red[t] += red[t+st]; __syncthreads(); }
    float mu = red[0] * (1.0f/384.0f);
    __syncthreads();

    float sq = 0.f;
    #pragma unroll
    for (int i = 0; i < 3; i++) { float d = v[i] - mu; sq += d*d; }
    red[t] = sq; __syncthreads();
    for (int st = 64; st > 0; st >>= 1) { if (t < st) red[t] += red[t+st]; __syncthreads(); }
    float var = red[0] * (1.0f/384.0f);
    float rs = rsqrtf(var + 1e-5f);
    __syncthreads();

    float pd0 = 0.f, pd1 = 0.f;
    #pragma unroll
    for (int i = 0; i < 3; i++) {
        int f = t + i*128;
        float zn = (v[i] - mu) * rs * ln_w[f] + ln_b[f];
        g_z[row*ZDIM + f] = zn;
        pd0 += g_c0[f] * zn;
        pd1 += dec_b[f] * zn;
    }
    red[t] = pd0; __syncthreads();
    for (int st = 64; st > 0; st >>= 1) { if (t < st) red[t] += red[t+st]; __syncthreads(); }
    if (t == 0) g_d0[row] = red[0];
    __syncthreads();
    red[t] = pd1; __syncthreads();
    for (int st = 64; st > 0; st >>= 1) { if (t < st) red[t] += red[t+st]; __syncthreads(); }
    if (t == 0) g_d1b[row] = red[0];
}

// ============ K3: three GEMMs, 384 fully-active CTAs ============
// bid [0,192):   op2 XV   = xh @ V_w        (512x384, transB, ldb=384)  16x12
// bid [192,288): op0 henc = gelu(z@enc_w+b) (512x192, transB, ldb=192)  16x6
// bid [288,384): op1 w    = z @ dec_w^T     (512x192, directB k-major)  16x6
__global__ __launch_bounds__(64) void k3_gemm(const float* __restrict__ enc_w,
                                              const float* __restrict__ enc_b,
                                              const float* __restrict__ dec_w,
                                              const float* __restrict__ V_w) {
    __shared__ __align__(16) float As[2][BM][36];
    __shared__ __align__(16) float Bs[2][BN][36];
    const int bid = blockIdx.x;
    int op, bx, by;
    if (bid < 192)      { op = 2; bx = bid % 12;          by = bid / 12; }
    else if (bid < 288) { op = 0; int i = bid-192; bx = i % 6; by = i / 6; }
    else                { op = 1; int i = bid-288; bx = i % 6; by = i / 6; }
    const int n0 = bx*BN, m0 = by*BM;

    const int t  = threadIdx.x;
    const int tx = t & 7, ty = t >> 3;
    const int lrow = t >> 1, half = t & 1;
    const int sw = lrow >> 2;

    const float* A  = (op == 2) ? g_xh : g_z;
    const float* Bt = (op == 0) ? enc_w : V_w;        // transB sources
    const int    ldb = (op == 0) ? HID : FEAT;

    ull acc[4][4];
    #pragma unroll
    for (int m = 0; m < 4; m++)
        #pragma unroll
        for (int n = 0; n < 4; n++) acc[m][n] = 0ULL;

    float4 sa[4], sb[4];
    const float* Arow = A + (m0 + lrow)*ZDIM + half*16;
    const float* Btk  = Bt + lrow*ldb + n0 + half*16;                 // transB: k-row = lrow
    const float* Bdk  = dec_w + (n0 + lrow)*ZDIM + half*16;           // direct: n-row = lrow

    #pragma unroll
    for (int j = 0; j < 4; j++) sa[j] = *(const float4*)(Arow + 4*j);
    if (op != 1) {
        #pragma unroll
        for (int j = 0; j < 4; j++) sb[j] = *(const float4*)(Btk + 4*j);
    } else {
        #pragma unroll
        for (int j = 0; j < 4; j++) sb[j] = *(const float4*)(Bdk + 4*j);
    }
    #pragma unroll
    for (int j = 0; j < 4; j++)
        *(float4*)&As[0][lrow][((4*half + j) ^ sw) * 4] = sa[j];
    if (op != 1) {
        #pragma unroll
        for (int j = 0; j < 4; j++) {
            const int cb = (sw ^ (4*half + j)) * 4 + (lrow & 3);
            const int nl = half*16 + 4*j;
            Bs[0][nl+0][cb] = sb[j].x;
            Bs[0][nl+1][cb] = sb[j].y;
            Bs[0][nl+2][cb] = sb[j].z;
            Bs[0][nl+3][cb] = sb[j].w;
        }
    } else {
        #pragma unroll
        for (int j = 0; j < 4; j++)
            *(float4*)&Bs[0][lrow][((4*half + j) ^ sw) * 4] = sb[j];
    }
    __syncthreads();

    int buf = 0;
    #pragma unroll 1
    for (int kt = 0; kt < ZDIM/BK; kt++) {
        if (kt < ZDIM/BK - 1) {
            const int kb = (kt+1)*BK;
            #pragma unroll
            for (int j = 0; j < 4; j++) sa[j] = *(const float4*)(Arow + kb + 4*j);
            if (op != 1) {
                #pragma unroll
                for (int j = 0; j < 4; j++) sb[j] = *(const float4*)(Btk + kb*ldb + 4*j);
            } else {
                #pragma unroll
                for (int j = 0; j < 4; j++) sb[j] = *(const float4*)(Bdk + kb + 4*j);
            }
        }
        #pragma unroll
        for (int q = 0; q < 8; q++) {
            ulonglong2 av[4], bv[4];
            #pragma unroll
            for (int m = 0; m < 4; m++)
                av[m] = *(const ulonglong2*)&As[buf][4*ty + m][(q ^ ty) * 4];
            #pragma unroll
            for (int n = 0; n < 4; n++)
                bv[n] = *(const ulonglong2*)&Bs[buf][4*tx + n][(q ^ tx) * 4];
            #pragma unroll
            for (int m = 0; m < 4; m++)
                #pragma unroll
                for (int n = 0; n < 4; n++) {
                    fma2(acc[m][n], av[m].x, bv[n].x);
                    fma2(acc[m][n], av[m].y, bv[n].y);
                }
        }
        if (kt < ZDIM/BK - 1) {
            const int nb = buf ^ 1;
            #pragma unroll
            for (int j = 0; j < 4; j++)
                *(float4*)&As[nb][lrow][((4*half + j) ^ sw) * 4] = sa[j];
            if (op != 1) {
                #pragma unroll
                for (int j = 0; j < 4; j++) {
                    const int cb = (sw ^ (4*half + j)) * 4 + (lrow & 3);
                    const int nl = half*16 + 4*j;
                    Bs[nb][nl+0][cb] = sb[j].x;
                    Bs[nb][nl+1][cb] = sb[j].y;
                    Bs[nb][nl+2][cb] = sb[j].z;
                    Bs[nb][nl+3][cb] = sb[j].w;
                }
            } else {
                #pragma unroll
                for (int j = 0; j < 4; j++)
                    *(float4*)&Bs[nb][lrow][((4*half + j) ^ sw) * 4] = sb[j];
            }
            __syncthreads();
            buf ^= 1;
        }
    }

    const int gcol = n0 + 4*tx;
    const int grow = m0 + 4*ty;
    if (op == 0) {
        const float4 b4 = *(const float4*)(enc_b + gcol);
        #pragma unroll
        for (int m = 0; m < 4; m++) {
            float4 r;
            r.x = gelu_f(accsum(acc[m][0]) + b4.x);
            r.y = gelu_f(accsum(acc[m][1]) + b4.y);
            r.z = gelu_f(accsum(acc[m][2]) + b4.z);
            r.w = gelu_f(accsum(acc[m][3]) + b4.w);
            *(float4*)&g_henc[(grow + m)*HID + gcol] = r;
        }
    } else if (op == 1) {
        #pragma unroll
        for (int m = 0; m < 4; m++) {
            float4 r;
            r.x = accsum(acc[m][0]); r.y = accsum(acc[m][1]);
            r.z = accsum(acc[m][2]); r.w = accsum(acc[m][3]);
            *(float4*)&g_w[(grow + m)*HID + gcol] = r;
        }
    } else {
        #pragma unroll
        for (int m = 0; m < 4; m++) {
            float4 r;
            r.x = accsum(acc[m][0]); r.y = accsum(acc[m][1]);
            r.z = accsum(acc[m][2]); r.w = accsum(acc[m][3]);
            *(float4*)&g_XV[(grow + m)*FEAT + gcol] = r;
        }
    }
}

// ============ K4: per batch — d1, softmax collapse, alpha/beta, T ============
__global__ __launch_bounds__(384) void k4_batch() {
    const int b = blockIdx.x;
    const int t = threadIdx.x;
    __shared__ float sd0[128], sd1[128], sE0[128], red[128];

    if (t < 128) sd0[t] = g_d0[b*128 + t];

    const int wid = t >> 5, lane = t & 31;
    for (int i = wid; i < 128; i += 12) {
        int g = b*128 + i;
        float acc = 0.f;
        #pragma unroll
        for (int j = 0; j < 6; j++) {
            int h = lane + j*32;
            acc += g_henc[g*HID + h] * g_w[g*HID + h];
        }
        #pragma unroll
        for (int o = 16; o; o >>= 1) acc += __shfl_xor_sync(0xffffffffu, acc, o);
        if (lane == 0) sd1[i] = acc + g_d1b[g];
    }
    __syncthreads();

    if (t < 128) red[t] = fmaxf(sd0[t], sd1[t]);
    __syncthreads();
    for (int st = 64; st > 0; st >>= 1) { if (t < st) red[t] = fmaxf(red[t], red[t+st]); __syncthreads(); }
    float M = red[0];
    __syncthreads();

    float e0 = 0.f, e1 = 0.f;
    if (t < 128) {
        e0 = expf(sd0[t] - M);
        e1 = expf(sd1[t] - M);
        sE0[t] = e0;
        red[t] = e0;
    }
    __syncthreads();
    for (int st = 64; st > 0; st >>= 1) { if (t < st) red[t] += red[t+st]; __syncthreads(); }
    float Ssum = red[0];

    if (t < 128) {
        float S = Ssum - e0 + e1;
        float a = 1.0f / S;
        g_alpha[b*128 + t] = a;
        g_beta [b*128 + t] = (e1 - e0) * a;
    }

    float acc = 0.f;
    #pragma unroll 4
    for (int j = 0; j < 128; j++) acc += sE0[j] * g_xh[(b*128 + j)*ZDIM + t];
    g_T[b*ZDIM + t] = acc;
}

// ============ K45: TV = T@V_w fused with final combine ============
__global__ __launch_bounds__(128) void k45_out(const float* __restrict__ V_w,
                                               const float* __restrict__ V_b,
                                               float* __restrict__ out) {
    const int b = blockIdx.x;
    const int t = threadIdx.x;
    const int f = blockIdx.y * 128 + t;
    __shared__ float sT[ZDIM];
    __shared__ float sA[128], sB[128];
    sT[t]       = g_T[b*ZDIM + t];
    sT[t + 128] = g_T[b*ZDIM + t + 128];
    sT[t + 256] = g_T[b*ZDIM + t + 256];
    sA[t] = g_alpha[b*128 + t];
    sB[t] = g_beta [b*128 + t];
    __syncthreads();

    float acc = 0.f;
    #pragma unroll 8
    for (int k = 0; k < ZDIM; k++) acc += sT[k] * V_w[k*FEAT + f];
    const float vb = V_b[f];

    #pragma unroll 4
    for (int r = 0; r < 128; r++) {
        const int m = b*128 + r;
        out[m*FEAT + f] = sA[r] * acc + sB[r] * g_XV[m*FEAT + f] + vb;
    }
}

// ---------------- launch ----------------
extern "C" void kernel_launch(void* const* d_in, const int* in_sizes, int n_in,
                              void* d_out, int out_size) {
    const float* x     = (const float*)d_in[0];
    const float* U_w   = (const float*)d_in[1];
    const float* U_b   = (const float*)d_in[2];
    const float* ln_w  = (const float*)d_in[3];
    const float* ln_b  = (const float*)d_in[4];
    const float* enc_w = (const float*)d_in[5];
    const float* enc_b = (const float*)d_in[6];
    const float* dec_w = (const float*)d_in[7];
    const float* dec_b = (const float*)d_in[8];
    const float* V_w   = (const float*)d_in[9];
    const float* V_b   = (const float*)d_in[10];
    float* out = (float*)d_out;

    k1_gemm<<<385, 64>>>(x, U_w, U_b, enc_b, dec_w, dec_b);
    k2_ln<<<ROWS, 128>>>(ln_w, ln_b, dec_b);
    k3_gemm<<<384, 64>>>(enc_w, enc_b, dec_w, V_w);
    k4_batch<<<BB, 384>>>();
    k45_out<<<dim3(BB, 3), 128>>>(V_w, V_b, out);
}